// round 15
// baseline (speedup 1.0000x reference)
#include <cuda_runtime.h>
#include <cstdint>
#include <cuda_bf16.h>
#include <mma.h>
#include <math.h>
#include <type_traits>

using namespace nvcuda;

#define BB 2
#define CC 512
#define HW 4096
#define NG 32
#define CPG 16
#define NQKV 1536

// ---- scratch ----
__device__ __align__(256) __nv_bfloat16 g_hn[BB * CC * HW];             // 8 MB
__device__ __align__(256) __nv_bfloat16 g_qkv[BB * NQKV * HW];          // 25 MB
__device__ __align__(256) __nv_bfloat16 g_scores[(size_t)BB * HW * HW]; // 67 MB
__device__ __align__(256) __nv_bfloat16 g_attn[(size_t)BB * HW * HW];   // 67 MB
__device__ __align__(256) __nv_bfloat16 g_ao[BB * CC * HW];             // 8 MB
__device__ __align__(256) __nv_bfloat16 g_qw_h[NQKV * CC];
__device__ __align__(256) __nv_bfloat16 g_pw_h[CC * CC];
__device__ __align__(256) float g_gnstat[BB * NG * 8 * 2];

// ============================================================
// cp.async helpers
// ============================================================
__device__ __forceinline__ void cp_async16(void* sdst, const void* gsrc) {
    unsigned s = (unsigned)__cvta_generic_to_shared(sdst);
    asm volatile("cp.async.ca.shared.global [%0], [%1], 16;\n" :: "r"(s), "l"(gsrc));
}
__device__ __forceinline__ void cp_commit() {
    asm volatile("cp.async.commit_group;\n");
}
template<int N> __device__ __forceinline__ void cp_wait() {
    asm volatile("cp.async.wait_group %0;\n" :: "n"(N));
}

// ---- bf16 GEMM smem layout: 256x128 block tile, BK=32, 3 stages ----
template<bool AROW, bool BROW>
struct BigLay {
    static const int LDA  = AROW ? 48 : 264;           // elems
    static const int LDB  = BROW ? 144 : 48;
    static const int ASTG = AROW ? 256 * 48 : 32 * 264;
    static const int BSTG = BROW ? 32 * 144 : 128 * 48;
    static const int STG  = ASTG + BSTG;
    static const int PIPE = 3 * STG * 2;               // bytes, 3 stages
    static const int BYTES = (PIPE > 67584) ? PIPE : 67584;   // vs epilogue staging
};

// ============================================================
// fp32 -> bf16 conversion (both weight tensors, one launch)
// ============================================================
__global__ void cvt2_kernel(const float* __restrict__ s0, __nv_bfloat16* __restrict__ d0, int n0,
                            const float* __restrict__ s1, __nv_bfloat16* __restrict__ d1, int n1)
{
    for (int i = blockIdx.x * blockDim.x + threadIdx.x; i < n0; i += gridDim.x * blockDim.x)
        d0[i] = __float2bfloat16(s0[i]);
    for (int i = blockIdx.x * blockDim.x + threadIdx.x; i < n1; i += gridDim.x * blockDim.x)
        d1[i] = __float2bfloat16(s1[i]);
}

// ============================================================
// GroupNorm phase 1: partial sums. grid = BB*NG*8, block 256.
// ============================================================
__global__ void __launch_bounds__(256) gn_stats(
    const float* __restrict__ x, float* __restrict__ stat)
{
    const size_t base = (size_t)blockIdx.x * 8192;
    const float4* xp = (const float4*)(x + base);
    float s = 0.f, ss = 0.f;
#pragma unroll
    for (int k = 0; k < 8; k++) {
        float4 v = xp[k * 256 + threadIdx.x];
        s  += v.x + v.y + v.z + v.w;
        ss += v.x * v.x + v.y * v.y + v.z * v.z + v.w * v.w;
    }
    __shared__ float sh_s[8], sh_q[8];
    for (int o = 16; o; o >>= 1) {
        s  += __shfl_down_sync(0xffffffffu, s, o);
        ss += __shfl_down_sync(0xffffffffu, ss, o);
    }
    int warp = threadIdx.x >> 5, lane = threadIdx.x & 31;
    if (lane == 0) { sh_s[warp] = s; sh_q[warp] = ss; }
    __syncthreads();
    if (threadIdx.x == 0) {
        float ts = 0.f, tq = 0.f;
#pragma unroll
        for (int i = 0; i < 8; i++) { ts += sh_s[i]; tq += sh_q[i]; }
        stat[blockIdx.x * 2]     = ts;
        stat[blockIdx.x * 2 + 1] = tq;
    }
}

// ============================================================
// GroupNorm phase 2: apply. grid = BB*CC, 256 thr.
// ============================================================
__global__ void __launch_bounds__(256) gn_apply(
    const float* __restrict__ x, const float* __restrict__ stat,
    const float* __restrict__ gamma, const float* __restrict__ beta,
    __nv_bfloat16* __restrict__ hn)
{
    const int bc = blockIdx.x;
    const int ch = bc & (CC - 1);
    const int bg = bc >> 4;
    __shared__ float sh[2];
    if (threadIdx.x == 0) {
        float s = 0.f, q = 0.f;
#pragma unroll
        for (int i = 0; i < 8; i++) {
            s += stat[(bg * 8 + i) * 2];
            q += stat[(bg * 8 + i) * 2 + 1];
        }
        const float inv_n = 1.f / (float)(CPG * HW);
        float mean = s * inv_n;
        float var  = q * inv_n - mean * mean;
        sh[0] = mean;
        sh[1] = rsqrtf(var + 1e-6f);
    }
    __syncthreads();
    const float mean = sh[0], rstd = sh[1];
    const float a = rstd * gamma[ch];
    const float b = beta[ch] - mean * a;

    const float4* xp = (const float4*)(x + (size_t)bc * HW);
    __nv_bfloat162* o2 = (__nv_bfloat162*)(hn + (size_t)bc * HW);
#pragma unroll
    for (int k = 0; k < 4; k++) {
        int i = k * 256 + threadIdx.x;
        float4 v = xp[i];
        o2[2 * i]     = __floats2bfloat162_rn(v.x * a + b, v.y * a + b);
        o2[2 * i + 1] = __floats2bfloat162_rn(v.z * a + b, v.w * a + b);
    }
}

// ============================================================
// BF16 tensor-core GEMM, 256x128 block tile, warp tile 64x64, 3-stage pipe.
// (R13 configuration — best measured: 522.8 us total.)
// C = alpha*op(A)*op(B) (+bias)(+resid fp32)
// ============================================================
template<bool AROW, bool BROW, typename OUT>
__global__ void __launch_bounds__(256) gemm_big(
    const __nv_bfloat16* __restrict__ A, const __nv_bfloat16* __restrict__ B,
    const float* __restrict__ bias, const float* __restrict__ Rsd,
    OUT* __restrict__ C,
    int K, int N, int lda, int ldb,
    size_t aStride, size_t bStride, size_t cStride, size_t rStride,
    float alpha)
{
    extern __shared__ char smem_c[];
    __nv_bfloat16* smemh = (__nv_bfloat16*)smem_c;
    using L = BigLay<AROW, BROW>;
    const int bz = blockIdx.z;
    A += aStride * bz; B += bStride * bz; C += cStride * bz;
    const float* R = Rsd ? (Rsd + rStride * bz) : nullptr;
    const int m0 = blockIdx.y * 256, n0 = blockIdx.x * 128;

    const int t = threadIdx.x;
    const int wid = t >> 5;
    const int wm = wid & 3;          // 4 warps x 64 rows
    const int wn = wid >> 2;         // 2 warps x 64 cols

    using ALay = typename std::conditional<AROW, wmma::row_major, wmma::col_major>::type;
    using BLay = typename std::conditional<BROW, wmma::row_major, wmma::col_major>::type;
    wmma::fragment<wmma::matrix_a, 16, 16, 16, __nv_bfloat16, ALay> af[4];
    wmma::fragment<wmma::matrix_b, 16, 16, 16, __nv_bfloat16, BLay> bf[4];
    wmma::fragment<wmma::accumulator, 16, 16, 16, float> acc[4][4];
#pragma unroll
    for (int i = 0; i < 4; i++)
#pragma unroll
        for (int j = 0; j < 4; j++)
            wmma::fill_fragment(acc[i][j], 0.f);

    auto load_stage = [&](int st, int k0) {
        __nv_bfloat16* As = smemh + st * L::STG;
        __nv_bfloat16* Bs = As + L::ASTG;
#pragma unroll
        for (int c = t; c < 1024; c += 256) {
            if (AROW) {                    // 256 rows x 32 k
                int m = c >> 2, kk = (c & 3) << 3;
                cp_async16(As + m * L::LDA + kk, A + (size_t)(m0 + m) * lda + k0 + kk);
            } else {                       // 32 k-rows x 256 m
                int k = c >> 5, mm = (c & 31) << 3;
                cp_async16(As + k * L::LDA + mm, A + (size_t)(k0 + k) * lda + m0 + mm);
            }
        }
#pragma unroll
        for (int c = t; c < 512; c += 256) {
            if (BROW) {                    // 32 k-rows x 128 n
                int k = c >> 4, nn = (c & 15) << 3;
                cp_async16(Bs + k * L::LDB + nn, B + (size_t)(k0 + k) * ldb + n0 + nn);
            } else {                       // 128 n-rows x 32 k
                int n = c >> 2, kk = (c & 3) << 3;
                cp_async16(Bs + n * L::LDB + kk, B + (size_t)(n0 + n) * ldb + k0 + kk);
            }
        }
    };

    const int KT = K >> 5;
    // 3-stage prologue: stages 0, 1 in flight
    load_stage(0, 0);
    cp_commit();
    if (KT > 1) load_stage(1, 32);
    cp_commit();

    int sidx = 0;                    // kt % 3
    for (int kt = 0; kt < KT; kt++) {
        int pf = kt + 2;
        if (pf < KT) {
            int pb = pf - 3 * (pf / 3);
            load_stage(pb, pf << 5);
        }
        cp_commit();                 // uniform group accounting
        cp_wait<2>();                // stage kt resident
        __syncthreads();

        const __nv_bfloat16* As = smemh + sidx * L::STG;
        const __nv_bfloat16* Bs = As + L::ASTG;
#pragma unroll
        for (int ks = 0; ks < 32; ks += 16) {
#pragma unroll
            for (int i = 0; i < 4; i++) {
                const __nv_bfloat16* ap = AROW
                    ? As + (wm * 64 + i * 16) * L::LDA + ks
                    : As + ks * L::LDA + (wm * 64 + i * 16);
                wmma::load_matrix_sync(af[i], ap, L::LDA);
            }
#pragma unroll
            for (int j = 0; j < 4; j++) {
                const __nv_bfloat16* bp = BROW
                    ? Bs + ks * L::LDB + (wn * 64 + j * 16)
                    : Bs + (wn * 64 + j * 16) * L::LDB + ks;
                wmma::load_matrix_sync(bf[j], bp, L::LDB);
            }
#pragma unroll
            for (int i = 0; i < 4; i++)
#pragma unroll
                for (int j = 0; j < 4; j++)
                    wmma::mma_sync(acc[i][j], af[i], bf[j], acc[i][j]);
        }
        __syncthreads();
        if (++sidx == 3) sidx = 0;
    }

    // ---- epilogue: two 128-row halves through 128x132 fp32 staging ----
    float* Csh = (float*)smem_c;
#pragma unroll
    for (int h = 0; h < 2; h++) {
        if ((wm >> 1) == h) {
#pragma unroll
            for (int i = 0; i < 4; i++)
#pragma unroll
                for (int j = 0; j < 4; j++)
                    wmma::store_matrix_sync(
                        Csh + ((wm & 1) * 64 + i * 16) * 132 + wn * 64 + j * 16,
                        acc[i][j], 132, wmma::mem_row_major);
        }
        __syncthreads();

        const int c4 = (t & 31) << 2;
        for (int r = t >> 5; r < 128; r += 8) {
            float4 v = *(const float4*)(Csh + r * 132 + c4);
            const int m = m0 + h * 128 + r;
            float bsv = bias ? bias[m] : 0.f;
            v.x = v.x * alpha + bsv;
            v.y = v.y * alpha + bsv;
            v.z = v.z * alpha + bsv;
            v.w = v.w * alpha + bsv;
            if (R) {
                float4 rv = *(const float4*)(R + (size_t)m * N + n0 + c4);
                v.x += rv.x; v.y += rv.y; v.z += rv.z; v.w += rv.w;
            }
            OUT* cp = C + (size_t)m * N + n0 + c4;
            if (std::is_same<OUT, float>::value) {
                *(float4*)(void*)cp = v;
            } else {
                ushort4 u;
                u.x = __bfloat16_as_ushort(__float2bfloat16(v.x));
                u.y = __bfloat16_as_ushort(__float2bfloat16(v.y));
                u.z = __bfloat16_as_ushort(__float2bfloat16(v.z));
                u.w = __bfloat16_as_ushort(__float2bfloat16(v.w));
                *(ushort4*)(void*)cp = u;
            }
        }
        __syncthreads();
    }
}

// ============================================================
// Softmax: uint4 (16B) loads/stores, row cached in 16 regs.
// ============================================================
__global__ void __launch_bounds__(256) softmax_kernel(
    const __nv_bfloat16* __restrict__ S, __nv_bfloat16* __restrict__ Aout)
{
    const uint4* row4 = (const uint4*)(S + (size_t)blockIdx.x * HW);
    uint4* out4 = (uint4*)(Aout + (size_t)blockIdx.x * HW);
    const int t = threadIdx.x;
    __shared__ float sh[8];

    // 2 x 16B loads per thread -> 16 fp32 values
    uint4 d0 = row4[t];
    uint4 d1 = row4[t + 256];
    float vals[16];
    {
        const unsigned w[8] = {d0.x, d0.y, d0.z, d0.w, d1.x, d1.y, d1.z, d1.w};
#pragma unroll
        for (int k = 0; k < 8; k++) {
            __nv_bfloat162 h = *(const __nv_bfloat162*)&w[k];
            float2 f = __bfloat1622float2(h);
            vals[2 * k] = f.x; vals[2 * k + 1] = f.y;
        }
    }

    float m = -1e30f;
#pragma unroll
    for (int k = 0; k < 16; k++) m = fmaxf(m, vals[k]);
    for (int o = 16; o; o >>= 1) m = fmaxf(m, __shfl_xor_sync(0xffffffffu, m, o));
    if ((t & 31) == 0) sh[t >> 5] = m;
    __syncthreads();
    m = sh[0];
#pragma unroll
    for (int i = 1; i < 8; i++) m = fmaxf(m, sh[i]);

    float s = 0.f;
#pragma unroll
    for (int k = 0; k < 16; k++) {
        float e = __expf(vals[k] - m);
        vals[k] = e;
        s += e;
    }
    for (int o = 16; o; o >>= 1) s += __shfl_xor_sync(0xffffffffu, s, o);
    __syncthreads();
    if ((t & 31) == 0) sh[t >> 5] = s;
    __syncthreads();
    s = 0.f;
#pragma unroll
    for (int i = 0; i < 8; i++) s += sh[i];
    float inv = 1.f / s;

    unsigned wo[8];
#pragma unroll
    for (int k = 0; k < 8; k++) {
        __nv_bfloat162 h = __floats2bfloat162_rn(vals[2 * k] * inv, vals[2 * k + 1] * inv);
        wo[k] = *(const unsigned*)&h;
    }
    out4[t]       = make_uint4(wo[0], wo[1], wo[2], wo[3]);
    out4[t + 256] = make_uint4(wo[4], wo[5], wo[6], wo[7]);
}

// ============================================================
// Launch
// ============================================================
extern "C" void kernel_launch(void* const* d_in, const int* in_sizes, int n_in,
                              void* d_out, int out_size)
{
    const float* x      = (const float*)d_in[0];
    const float* gamma  = (const float*)d_in[1];
    const float* beta   = (const float*)d_in[2];
    const float* qkv_w  = (const float*)d_in[3];
    const float* qkv_b  = (const float*)d_in[4];
    const float* proj_w = (const float*)d_in[5];
    const float* proj_b = (const float*)d_in[6];
    float* out = (float*)d_out;

    __nv_bfloat16 *hn, *qkv, *scores, *attn, *ao, *qw, *pw;
    float* stat;
    cudaGetSymbolAddress((void**)&hn, g_hn);
    cudaGetSymbolAddress((void**)&qkv, g_qkv);
    cudaGetSymbolAddress((void**)&scores, g_scores);
    cudaGetSymbolAddress((void**)&attn, g_attn);
    cudaGetSymbolAddress((void**)&ao, g_ao);
    cudaGetSymbolAddress((void**)&qw, g_qw_h);
    cudaGetSymbolAddress((void**)&pw, g_pw_h);
    cudaGetSymbolAddress((void**)&stat, g_gnstat);

    cudaFuncSetAttribute(gemm_big<true,  true,  __nv_bfloat16>, cudaFuncAttributeMaxDynamicSharedMemorySize, BigLay<true,  true >::BYTES);
    cudaFuncSetAttribute(gemm_big<false, true,  __nv_bfloat16>, cudaFuncAttributeMaxDynamicSharedMemorySize, BigLay<false, true >::BYTES);
    cudaFuncSetAttribute(gemm_big<true,  false, __nv_bfloat16>, cudaFuncAttributeMaxDynamicSharedMemorySize, BigLay<true,  false>::BYTES);
    cudaFuncSetAttribute(gemm_big<true,  true,  float>,         cudaFuncAttributeMaxDynamicSharedMemorySize, BigLay<true,  true >::BYTES);

    // 0) weight conversions (single launch)
    cvt2_kernel<<<264, 256>>>(qkv_w, qw, NQKV * CC, proj_w, pw, CC * CC);

    // 1) GroupNorm stats
    gn_stats<<<BB * NG * 8, 256>>>(x, stat);

    // 2) GroupNorm apply -> bf16 hn
    gn_apply<<<BB * CC, 256>>>(x, stat, gamma, beta, hn);

    // 3) QKV = W_qkv @ hn + b
    {
        dim3 grid(HW / 128, NQKV / 256, BB);
        gemm_big<true, true, __nv_bfloat16><<<grid, 256, BigLay<true, true>::BYTES>>>(
            qw, hn, qkv_b, nullptr, qkv,
            CC, HW, CC, HW,
            0, (size_t)CC * HW, (size_t)NQKV * HW, 0, 1.f);
    }

    // 4) scores = scale * Q^T K
    {
        dim3 grid(HW / 128, HW / 256, BB);
        gemm_big<false, true, __nv_bfloat16><<<grid, 256, BigLay<false, true>::BYTES>>>(
            qkv, qkv + (size_t)CC * HW, nullptr, nullptr, scores,
            CC, HW, HW, HW,
            (size_t)NQKV * HW, (size_t)NQKV * HW, (size_t)HW * HW, 0,
            0.04419417382415922f);
    }

    // 5) softmax rows -> bf16
    softmax_kernel<<<BB * HW, 256>>>(scores, attn);

    // 6) attnout = V @ attn^T
    {
        dim3 grid(HW / 128, CC / 256, BB);
        gemm_big<true, false, __nv_bfloat16><<<grid, 256, BigLay<true, false>::BYTES>>>(
            qkv + (size_t)2 * CC * HW, attn, nullptr, nullptr, ao,
            HW, HW, HW, HW,
            (size_t)NQKV * HW, (size_t)HW * HW, (size_t)CC * HW, 0, 1.f);
    }

    // 7) out = x + proj_w @ attnout + proj_b
    {
        dim3 grid(HW / 128, CC / 256, BB);
        gemm_big<true, true, float><<<grid, 256, BigLay<true, true>::BYTES>>>(
            pw, ao, proj_b, x, out,
            CC, HW, CC, HW,
            0, (size_t)CC * HW, (size_t)CC * HW, (size_t)CC * HW, 1.f);
    }
}

// round 16
// speedup vs baseline: 1.5215x; 1.5215x over previous
#include <cuda_runtime.h>
#include <cstdint>
#include <cuda_bf16.h>
#include <mma.h>
#include <math.h>
#include <type_traits>

using namespace nvcuda;

#define BB 2
#define CC 512
#define HW 4096
#define NG 32
#define CPG 16
#define NQKV 1536

// ---- scratch ----
__device__ __align__(256) __nv_bfloat16 g_hn[BB * CC * HW];             // 8 MB
__device__ __align__(256) __nv_bfloat16 g_qkv[BB * NQKV * HW];          // 25 MB
__device__ __align__(256) __nv_bfloat16 g_scores[(size_t)BB * HW * HW]; // 67 MB
__device__ __align__(256) __nv_bfloat16 g_attn[(size_t)BB * HW * HW];   // 67 MB
__device__ __align__(256) __nv_bfloat16 g_ao[BB * CC * HW];             // 8 MB
__device__ __align__(256) __nv_bfloat16 g_qw_h[NQKV * CC];
__device__ __align__(256) __nv_bfloat16 g_pw_h[CC * CC];
__device__ __align__(256) float g_gnstat[BB * NG * 8 * 2];

// ============================================================
// cp.async helpers
// ============================================================
__device__ __forceinline__ void cp_async16(void* sdst, const void* gsrc) {
    unsigned s = (unsigned)__cvta_generic_to_shared(sdst);
    asm volatile("cp.async.ca.shared.global [%0], [%1], 16;\n" :: "r"(s), "l"(gsrc));
}
__device__ __forceinline__ void cp_commit() {
    asm volatile("cp.async.commit_group;\n");
}
template<int N> __device__ __forceinline__ void cp_wait() {
    asm volatile("cp.async.wait_group %0;\n" :: "n"(N));
}

// ---- bf16 GEMM smem layout: 256x128 block tile, BK=32, 3 stages ----
template<bool AROW, bool BROW>
struct BigLay {
    static const int LDA  = AROW ? 48 : 264;           // elems
    static const int LDB  = BROW ? 144 : 48;
    static const int ASTG = AROW ? 256 * 48 : 32 * 264;
    static const int BSTG = BROW ? 32 * 144 : 128 * 48;
    static const int STG  = ASTG + BSTG;
    static const int PIPE = 3 * STG * 2;               // bytes, 3 stages
    static const int BYTES = (PIPE > 67584) ? PIPE : 67584;   // vs epilogue staging
};

// ============================================================
// fp32 -> bf16 conversion (both weight tensors, one launch)
// ============================================================
__global__ void cvt2_kernel(const float* __restrict__ s0, __nv_bfloat16* __restrict__ d0, int n0,
                            const float* __restrict__ s1, __nv_bfloat16* __restrict__ d1, int n1)
{
    for (int i = blockIdx.x * blockDim.x + threadIdx.x; i < n0; i += gridDim.x * blockDim.x)
        d0[i] = __float2bfloat16(s0[i]);
    for (int i = blockIdx.x * blockDim.x + threadIdx.x; i < n1; i += gridDim.x * blockDim.x)
        d1[i] = __float2bfloat16(s1[i]);
}

// ============================================================
// GroupNorm phase 1: partial sums. grid = BB*NG*8, block 256.
// ============================================================
__global__ void __launch_bounds__(256) gn_stats(
    const float* __restrict__ x, float* __restrict__ stat)
{
    const size_t base = (size_t)blockIdx.x * 8192;
    const float4* xp = (const float4*)(x + base);
    float s = 0.f, ss = 0.f;
#pragma unroll
    for (int k = 0; k < 8; k++) {
        float4 v = xp[k * 256 + threadIdx.x];
        s  += v.x + v.y + v.z + v.w;
        ss += v.x * v.x + v.y * v.y + v.z * v.z + v.w * v.w;
    }
    __shared__ float sh_s[8], sh_q[8];
    for (int o = 16; o; o >>= 1) {
        s  += __shfl_down_sync(0xffffffffu, s, o);
        ss += __shfl_down_sync(0xffffffffu, ss, o);
    }
    int warp = threadIdx.x >> 5, lane = threadIdx.x & 31;
    if (lane == 0) { sh_s[warp] = s; sh_q[warp] = ss; }
    __syncthreads();
    if (threadIdx.x == 0) {
        float ts = 0.f, tq = 0.f;
#pragma unroll
        for (int i = 0; i < 8; i++) { ts += sh_s[i]; tq += sh_q[i]; }
        stat[blockIdx.x * 2]     = ts;
        stat[blockIdx.x * 2 + 1] = tq;
    }
}

// ============================================================
// GroupNorm phase 2: apply. grid = BB*CC, 256 thr.
// ============================================================
__global__ void __launch_bounds__(256) gn_apply(
    const float* __restrict__ x, const float* __restrict__ stat,
    const float* __restrict__ gamma, const float* __restrict__ beta,
    __nv_bfloat16* __restrict__ hn)
{
    const int bc = blockIdx.x;
    const int ch = bc & (CC - 1);
    const int bg = bc >> 4;
    __shared__ float sh[2];
    if (threadIdx.x == 0) {
        float s = 0.f, q = 0.f;
#pragma unroll
        for (int i = 0; i < 8; i++) {
            s += stat[(bg * 8 + i) * 2];
            q += stat[(bg * 8 + i) * 2 + 1];
        }
        const float inv_n = 1.f / (float)(CPG * HW);
        float mean = s * inv_n;
        float var  = q * inv_n - mean * mean;
        sh[0] = mean;
        sh[1] = rsqrtf(var + 1e-6f);
    }
    __syncthreads();
    const float mean = sh[0], rstd = sh[1];
    const float a = rstd * gamma[ch];
    const float b = beta[ch] - mean * a;

    const float4* xp = (const float4*)(x + (size_t)bc * HW);
    __nv_bfloat162* o2 = (__nv_bfloat162*)(hn + (size_t)bc * HW);
#pragma unroll
    for (int k = 0; k < 4; k++) {
        int i = k * 256 + threadIdx.x;
        float4 v = xp[i];
        o2[2 * i]     = __floats2bfloat162_rn(v.x * a + b, v.y * a + b);
        o2[2 * i + 1] = __floats2bfloat162_rn(v.z * a + b, v.w * a + b);
    }
}

// ============================================================
// BF16 tensor-core GEMM, 256x128 block tile, warp tile 64x64, 3-stage pipe.
// C = alpha*op(A)*op(B) (+bias)(+resid fp32)
// ============================================================
template<bool AROW, bool BROW, typename OUT>
__global__ void __launch_bounds__(256) gemm_big(
    const __nv_bfloat16* __restrict__ A, const __nv_bfloat16* __restrict__ B,
    const float* __restrict__ bias, const float* __restrict__ Rsd,
    OUT* __restrict__ C,
    int K, int N, int lda, int ldb,
    size_t aStride, size_t bStride, size_t cStride, size_t rStride,
    float alpha)
{
    extern __shared__ char smem_c[];
    __nv_bfloat16* smemh = (__nv_bfloat16*)smem_c;
    using L = BigLay<AROW, BROW>;
    const int bz = blockIdx.z;
    A += aStride * bz; B += bStride * bz; C += cStride * bz;
    const float* R = Rsd ? (Rsd + rStride * bz) : nullptr;
    const int m0 = blockIdx.y * 256, n0 = blockIdx.x * 128;

    const int t = threadIdx.x;
    const int wid = t >> 5;
    const int wm = wid & 3;          // 4 warps x 64 rows
    const int wn = wid >> 2;         // 2 warps x 64 cols

    using ALay = typename std::conditional<AROW, wmma::row_major, wmma::col_major>::type;
    using BLay = typename std::conditional<BROW, wmma::row_major, wmma::col_major>::type;
    wmma::fragment<wmma::matrix_a, 16, 16, 16, __nv_bfloat16, ALay> af[4];
    wmma::fragment<wmma::matrix_b, 16, 16, 16, __nv_bfloat16, BLay> bf[4];
    wmma::fragment<wmma::accumulator, 16, 16, 16, float> acc[4][4];
#pragma unroll
    for (int i = 0; i < 4; i++)
#pragma unroll
        for (int j = 0; j < 4; j++)
            wmma::fill_fragment(acc[i][j], 0.f);

    auto load_stage = [&](int st, int k0) {
        __nv_bfloat16* As = smemh + st * L::STG;
        __nv_bfloat16* Bs = As + L::ASTG;
#pragma unroll
        for (int c = t; c < 1024; c += 256) {
            if (AROW) {                    // 256 rows x 32 k
                int m = c >> 2, kk = (c & 3) << 3;
                cp_async16(As + m * L::LDA + kk, A + (size_t)(m0 + m) * lda + k0 + kk);
            } else {                       // 32 k-rows x 256 m
                int k = c >> 5, mm = (c & 31) << 3;
                cp_async16(As + k * L::LDA + mm, A + (size_t)(k0 + k) * lda + m0 + mm);
            }
        }
#pragma unroll
        for (int c = t; c < 512; c += 256) {
            if (BROW) {                    // 32 k-rows x 128 n
                int k = c >> 4, nn = (c & 15) << 3;
                cp_async16(Bs + k * L::LDB + nn, B + (size_t)(k0 + k) * ldb + n0 + nn);
            } else {                       // 128 n-rows x 32 k
                int n = c >> 2, kk = (c & 3) << 3;
                cp_async16(Bs + n * L::LDB + kk, B + (size_t)(n0 + n) * ldb + k0 + kk);
            }
        }
    };

    const int KT = K >> 5;
    // 3-stage prologue: stages 0, 1 in flight
    load_stage(0, 0);
    cp_commit();
    if (KT > 1) load_stage(1, 32);
    cp_commit();

    int sidx = 0;                    // kt % 3
    for (int kt = 0; kt < KT; kt++) {
        int pf = kt + 2;
        if (pf < KT) {
            int pb = pf - 3 * (pf / 3);
            load_stage(pb, pf << 5);
        }
        cp_commit();                 // uniform group accounting
        cp_wait<2>();                // stage kt resident
        __syncthreads();

        const __nv_bfloat16* As = smemh + sidx * L::STG;
        const __nv_bfloat16* Bs = As + L::ASTG;
#pragma unroll
        for (int ks = 0; ks < 32; ks += 16) {
#pragma unroll
            for (int i = 0; i < 4; i++) {
                const __nv_bfloat16* ap = AROW
                    ? As + (wm * 64 + i * 16) * L::LDA + ks
                    : As + ks * L::LDA + (wm * 64 + i * 16);
                wmma::load_matrix_sync(af[i], ap, L::LDA);
            }
#pragma unroll
            for (int j = 0; j < 4; j++) {
                const __nv_bfloat16* bp = BROW
                    ? Bs + ks * L::LDB + (wn * 64 + j * 16)
                    : Bs + (wn * 64 + j * 16) * L::LDB + ks;
                wmma::load_matrix_sync(bf[j], bp, L::LDB);
            }
#pragma unroll
            for (int i = 0; i < 4; i++)
#pragma unroll
                for (int j = 0; j < 4; j++)
                    wmma::mma_sync(acc[i][j], af[i], bf[j], acc[i][j]);
        }
        __syncthreads();
        if (++sidx == 3) sidx = 0;
    }

    // ---- epilogue: two 128-row halves through 128x132 fp32 staging ----
    float* Csh = (float*)smem_c;
#pragma unroll
    for (int h = 0; h < 2; h++) {
        if ((wm >> 1) == h) {
#pragma unroll
            for (int i = 0; i < 4; i++)
#pragma unroll
                for (int j = 0; j < 4; j++)
                    wmma::store_matrix_sync(
                        Csh + ((wm & 1) * 64 + i * 16) * 132 + wn * 64 + j * 16,
                        acc[i][j], 132, wmma::mem_row_major);
        }
        __syncthreads();

        const int c4 = (t & 31) << 2;
        for (int r = t >> 5; r < 128; r += 8) {
            float4 v = *(const float4*)(Csh + r * 132 + c4);
            const int m = m0 + h * 128 + r;
            float bsv = bias ? bias[m] : 0.f;
            v.x = v.x * alpha + bsv;
            v.y = v.y * alpha + bsv;
            v.z = v.z * alpha + bsv;
            v.w = v.w * alpha + bsv;
            if (R) {
                float4 rv = *(const float4*)(R + (size_t)m * N + n0 + c4);
                v.x += rv.x; v.y += rv.y; v.z += rv.z; v.w += rv.w;
            }
            OUT* cp = C + (size_t)m * N + n0 + c4;
            if (std::is_same<OUT, float>::value) {
                *(float4*)(void*)cp = v;
            } else {
                ushort4 u;
                u.x = __bfloat16_as_ushort(__float2bfloat16(v.x));
                u.y = __bfloat16_as_ushort(__float2bfloat16(v.y));
                u.z = __bfloat16_as_ushort(__float2bfloat16(v.z));
                u.w = __bfloat16_as_ushort(__float2bfloat16(v.w));
                *(ushort4*)(void*)cp = u;
            }
        }
        __syncthreads();
    }
}

// ============================================================
// Softmax: single global read. Row (4096) cached in 16 regs/thread.
// ============================================================
__global__ void __launch_bounds__(256) softmax_kernel(
    const __nv_bfloat16* __restrict__ S, __nv_bfloat16* __restrict__ Aout)
{
    const __nv_bfloat162* row2 = (const __nv_bfloat162*)(S + (size_t)blockIdx.x * HW);
    __nv_bfloat162* arow2 = (__nv_bfloat162*)(Aout + (size_t)blockIdx.x * HW);
    const int t = threadIdx.x;
    __shared__ float sh[8];

    float vals[16];
    float m = -1e30f;
#pragma unroll
    for (int k = 0; k < 8; k++) {
        float2 f = __bfloat1622float2(row2[t + k * 256]);
        vals[2 * k] = f.x; vals[2 * k + 1] = f.y;
        m = fmaxf(m, fmaxf(f.x, f.y));
    }
    for (int o = 16; o; o >>= 1) m = fmaxf(m, __shfl_xor_sync(0xffffffffu, m, o));
    if ((t & 31) == 0) sh[t >> 5] = m;
    __syncthreads();
    m = sh[0];
#pragma unroll
    for (int i = 1; i < 8; i++) m = fmaxf(m, sh[i]);

    float s = 0.f;
#pragma unroll
    for (int k = 0; k < 16; k++) {
        float e = __expf(vals[k] - m);
        vals[k] = e;
        s += e;
    }
    for (int o = 16; o; o >>= 1) s += __shfl_xor_sync(0xffffffffu, s, o);
    __syncthreads();
    if ((t & 31) == 0) sh[t >> 5] = s;
    __syncthreads();
    s = 0.f;
#pragma unroll
    for (int i = 0; i < 8; i++) s += sh[i];
    float inv = 1.f / s;
#pragma unroll
    for (int k = 0; k < 8; k++)
        arow2[t + k * 256] = __floats2bfloat162_rn(vals[2 * k] * inv, vals[2 * k + 1] * inv);
}

// ============================================================
// Launch
// ============================================================
extern "C" void kernel_launch(void* const* d_in, const int* in_sizes, int n_in,
                              void* d_out, int out_size)
{
    const float* x      = (const float*)d_in[0];
    const float* gamma  = (const float*)d_in[1];
    const float* beta   = (const float*)d_in[2];
    const float* qkv_w  = (const float*)d_in[3];
    const float* qkv_b  = (const float*)d_in[4];
    const float* proj_w = (const float*)d_in[5];
    const float* proj_b = (const float*)d_in[6];
    float* out = (float*)d_out;

    __nv_bfloat16 *hn, *qkv, *scores, *attn, *ao, *qw, *pw;
    float* stat;
    cudaGetSymbolAddress((void**)&hn, g_hn);
    cudaGetSymbolAddress((void**)&qkv, g_qkv);
    cudaGetSymbolAddress((void**)&scores, g_scores);
    cudaGetSymbolAddress((void**)&attn, g_attn);
    cudaGetSymbolAddress((void**)&ao, g_ao);
    cudaGetSymbolAddress((void**)&qw, g_qw_h);
    cudaGetSymbolAddress((void**)&pw, g_pw_h);
    cudaGetSymbolAddress((void**)&stat, g_gnstat);

    cudaFuncSetAttribute(gemm_big<true,  true,  __nv_bfloat16>, cudaFuncAttributeMaxDynamicSharedMemorySize, BigLay<true,  true >::BYTES);
    cudaFuncSetAttribute(gemm_big<false, true,  __nv_bfloat16>, cudaFuncAttributeMaxDynamicSharedMemorySize, BigLay<false, true >::BYTES);
    cudaFuncSetAttribute(gemm_big<true,  false, __nv_bfloat16>, cudaFuncAttributeMaxDynamicSharedMemorySize, BigLay<true,  false>::BYTES);
    cudaFuncSetAttribute(gemm_big<true,  true,  float>,         cudaFuncAttributeMaxDynamicSharedMemorySize, BigLay<true,  true >::BYTES);

    // 0) weight conversions (single launch)
    cvt2_kernel<<<264, 256>>>(qkv_w, qw, NQKV * CC, proj_w, pw, CC * CC);

    // 1) GroupNorm stats
    gn_stats<<<BB * NG * 8, 256>>>(x, stat);

    // 2) GroupNorm apply -> bf16 hn
    gn_apply<<<BB * CC, 256>>>(x, stat, gamma, beta, hn);

    // 3) QKV = W_qkv @ hn + b
    {
        dim3 grid(HW / 128, NQKV / 256, BB);
        gemm_big<true, true, __nv_bfloat16><<<grid, 256, BigLay<true, true>::BYTES>>>(
            qw, hn, qkv_b, nullptr, qkv,
            CC, HW, CC, HW,
            0, (size_t)CC * HW, (size_t)NQKV * HW, 0, 1.f);
    }

    // 4) scores = scale * Q^T K
    {
        dim3 grid(HW / 128, HW / 256, BB);
        gemm_big<false, true, __nv_bfloat16><<<grid, 256, BigLay<false, true>::BYTES>>>(
            qkv, qkv + (size_t)CC * HW, nullptr, nullptr, scores,
            CC, HW, HW, HW,
            (size_t)NQKV * HW, (size_t)NQKV * HW, (size_t)HW * HW, 0,
            0.04419417382415922f);
    }

    // 5) softmax rows -> bf16
    softmax_kernel<<<BB * HW, 256>>>(scores, attn);

    // 6) attnout = V @ attn^T
    {
        dim3 grid(HW / 128, CC / 256, BB);
        gemm_big<true, false, __nv_bfloat16><<<grid, 256, BigLay<true, false>::BYTES>>>(
            qkv + (size_t)2 * CC * HW, attn, nullptr, nullptr, ao,
            HW, HW, HW, HW,
            (size_t)NQKV * HW, (size_t)HW * HW, (size_t)CC * HW, 0, 1.f);
    }

    // 7) out = x + proj_w @ attnout + proj_b
    {
        dim3 grid(HW / 128, CC / 256, BB);
        gemm_big<true, true, float><<<grid, 256, BigLay<true, true>::BYTES>>>(
            pw, ao, proj_b, x, out,
            CC, HW, CC, HW,
            0, (size_t)CC * HW, (size_t)CC * HW, (size_t)CC * HW, 1.f);
    }
}

// round 17
// speedup vs baseline: 1.5472x; 1.0169x over previous
#include <cuda_runtime.h>
#include <cstdint>
#include <cuda_bf16.h>
#include <mma.h>
#include <math.h>
#include <type_traits>

using namespace nvcuda;

#define BB 2
#define CC 512
#define HW 4096
#define NG 32
#define CPG 16
#define NQKV 1536

// ---- scratch ----
__device__ __align__(256) __nv_bfloat16 g_hn[BB * CC * HW];             // 8 MB
__device__ __align__(256) __nv_bfloat16 g_qkv[BB * NQKV * HW];          // 25 MB
__device__ __align__(256) __nv_bfloat16 g_scores[(size_t)BB * HW * HW]; // 67 MB
__device__ __align__(256) __nv_bfloat16 g_attn[(size_t)BB * HW * HW];   // 67 MB
__device__ __align__(256) __nv_bfloat16 g_ao[BB * CC * HW];             // 8 MB
__device__ __align__(256) __nv_bfloat16 g_qw_h[NQKV * CC];
__device__ __align__(256) __nv_bfloat16 g_pw_h[CC * CC];
__device__ __align__(256) float g_gnstat[BB * NG * 8 * 2];

// ============================================================
// cp.async helpers
// ============================================================
__device__ __forceinline__ void cp_async16(void* sdst, const void* gsrc) {
    unsigned s = (unsigned)__cvta_generic_to_shared(sdst);
    asm volatile("cp.async.ca.shared.global [%0], [%1], 16;\n" :: "r"(s), "l"(gsrc));
}
__device__ __forceinline__ void cp_commit() {
    asm volatile("cp.async.commit_group;\n");
}
template<int N> __device__ __forceinline__ void cp_wait() {
    asm volatile("cp.async.wait_group %0;\n" :: "n"(N));
}

// ---- bf16 GEMM smem layout: 256x128 block tile, BK=32, 3 stages ----
template<bool AROW, bool BROW>
struct BigLay {
    static const int LDA  = AROW ? 48 : 264;           // elems
    static const int LDB  = BROW ? 144 : 48;
    static const int ASTG = AROW ? 256 * 48 : 32 * 264;
    static const int BSTG = BROW ? 32 * 144 : 128 * 48;
    static const int STG  = ASTG + BSTG;
    static const int PIPE = 3 * STG * 2;               // bytes, 3 stages
    static const int BYTES = (PIPE > 67584) ? PIPE : 67584;   // vs epilogue staging
};

// ============================================================
// Fused: GroupNorm partial sums + weight fp32->bf16 conversion.
// grid = 1024: blocks [0,512) stats (8192 floats each),
//              blocks [512,1024) cvt (2048 weights each; boundary at 896).
// ============================================================
__global__ void __launch_bounds__(256) gn_stats_cvt(
    const float* __restrict__ x, float* __restrict__ stat,
    const float* __restrict__ qkvw, __nv_bfloat16* __restrict__ qw,
    const float* __restrict__ projw, __nv_bfloat16* __restrict__ pw)
{
    if (blockIdx.x < 512) {
        const size_t base = (size_t)blockIdx.x * 8192;
        const float4* xp = (const float4*)(x + base);
        float s = 0.f, ss = 0.f;
#pragma unroll
        for (int k = 0; k < 8; k++) {
            float4 v = xp[k * 256 + threadIdx.x];
            s  += v.x + v.y + v.z + v.w;
            ss += v.x * v.x + v.y * v.y + v.z * v.z + v.w * v.w;
        }
        __shared__ float sh_s[8], sh_q[8];
        for (int o = 16; o; o >>= 1) {
            s  += __shfl_down_sync(0xffffffffu, s, o);
            ss += __shfl_down_sync(0xffffffffu, ss, o);
        }
        int warp = threadIdx.x >> 5, lane = threadIdx.x & 31;
        if (lane == 0) { sh_s[warp] = s; sh_q[warp] = ss; }
        __syncthreads();
        if (threadIdx.x == 0) {
            float ts = 0.f, tq = 0.f;
#pragma unroll
            for (int i = 0; i < 8; i++) { ts += sh_s[i]; tq += sh_q[i]; }
            stat[blockIdx.x * 2]     = ts;
            stat[blockIdx.x * 2 + 1] = tq;
        }
    } else {
        const int local = blockIdx.x - 512;     // 0..511
        const float* src;
        __nv_bfloat16* dst;
        if (local < 384) {                      // qkv_w: 384 * 2048 = 786432
            src = qkvw + (size_t)local * 2048;
            dst = qw   + (size_t)local * 2048;
        } else {                                // proj_w: 128 * 2048 = 262144
            src = projw + (size_t)(local - 384) * 2048;
            dst = pw    + (size_t)(local - 384) * 2048;
        }
        const float4* s4 = (const float4*)src;
        float4 a = s4[threadIdx.x * 2];
        float4 b = s4[threadIdx.x * 2 + 1];
        __nv_bfloat162 h0 = __floats2bfloat162_rn(a.x, a.y);
        __nv_bfloat162 h1 = __floats2bfloat162_rn(a.z, a.w);
        __nv_bfloat162 h2 = __floats2bfloat162_rn(b.x, b.y);
        __nv_bfloat162 h3 = __floats2bfloat162_rn(b.z, b.w);
        uint4 o;
        o.x = *(const unsigned*)&h0;
        o.y = *(const unsigned*)&h1;
        o.z = *(const unsigned*)&h2;
        o.w = *(const unsigned*)&h3;
        ((uint4*)dst)[threadIdx.x] = o;
    }
}

// ============================================================
// GroupNorm phase 2: apply. grid = BB*CC, 256 thr.
// ============================================================
__global__ void __launch_bounds__(256) gn_apply(
    const float* __restrict__ x, const float* __restrict__ stat,
    const float* __restrict__ gamma, const float* __restrict__ beta,
    __nv_bfloat16* __restrict__ hn)
{
    const int bc = blockIdx.x;
    const int ch = bc & (CC - 1);
    const int bg = bc >> 4;
    __shared__ float sh[2];
    if (threadIdx.x == 0) {
        float s = 0.f, q = 0.f;
#pragma unroll
        for (int i = 0; i < 8; i++) {
            s += stat[(bg * 8 + i) * 2];
            q += stat[(bg * 8 + i) * 2 + 1];
        }
        const float inv_n = 1.f / (float)(CPG * HW);
        float mean = s * inv_n;
        float var  = q * inv_n - mean * mean;
        sh[0] = mean;
        sh[1] = rsqrtf(var + 1e-6f);
    }
    __syncthreads();
    const float mean = sh[0], rstd = sh[1];
    const float a = rstd * gamma[ch];
    const float b = beta[ch] - mean * a;

    const float4* xp = (const float4*)(x + (size_t)bc * HW);
    __nv_bfloat162* o2 = (__nv_bfloat162*)(hn + (size_t)bc * HW);
#pragma unroll
    for (int k = 0; k < 4; k++) {
        int i = k * 256 + threadIdx.x;
        float4 v = xp[i];
        o2[2 * i]     = __floats2bfloat162_rn(v.x * a + b, v.y * a + b);
        o2[2 * i + 1] = __floats2bfloat162_rn(v.z * a + b, v.w * a + b);
    }
}

// ============================================================
// BF16 tensor-core GEMM, 256x128 block tile, warp tile 64x64, 3-stage pipe.
// C = alpha*op(A)*op(B) (+bias)(+resid fp32)
// ============================================================
template<bool AROW, bool BROW, typename OUT>
__global__ void __launch_bounds__(256) gemm_big(
    const __nv_bfloat16* __restrict__ A, const __nv_bfloat16* __restrict__ B,
    const float* __restrict__ bias, const float* __restrict__ Rsd,
    OUT* __restrict__ C,
    int K, int N, int lda, int ldb,
    size_t aStride, size_t bStride, size_t cStride, size_t rStride,
    float alpha)
{
    extern __shared__ char smem_c[];
    __nv_bfloat16* smemh = (__nv_bfloat16*)smem_c;
    using L = BigLay<AROW, BROW>;
    const int bz = blockIdx.z;
    A += aStride * bz; B += bStride * bz; C += cStride * bz;
    const float* R = Rsd ? (Rsd + rStride * bz) : nullptr;
    const int m0 = blockIdx.y * 256, n0 = blockIdx.x * 128;

    const int t = threadIdx.x;
    const int wid = t >> 5;
    const int wm = wid & 3;          // 4 warps x 64 rows
    const int wn = wid >> 2;         // 2 warps x 64 cols

    using ALay = typename std::conditional<AROW, wmma::row_major, wmma::col_major>::type;
    using BLay = typename std::conditional<BROW, wmma::row_major, wmma::col_major>::type;
    wmma::fragment<wmma::matrix_a, 16, 16, 16, __nv_bfloat16, ALay> af[4];
    wmma::fragment<wmma::matrix_b, 16, 16, 16, __nv_bfloat16, BLay> bf[4];
    wmma::fragment<wmma::accumulator, 16, 16, 16, float> acc[4][4];
#pragma unroll
    for (int i = 0; i < 4; i++)
#pragma unroll
        for (int j = 0; j < 4; j++)
            wmma::fill_fragment(acc[i][j], 0.f);

    auto load_stage = [&](int st, int k0) {
        __nv_bfloat16* As = smemh + st * L::STG;
        __nv_bfloat16* Bs = As + L::ASTG;
#pragma unroll
        for (int c = t; c < 1024; c += 256) {
            if (AROW) {                    // 256 rows x 32 k
                int m = c >> 2, kk = (c & 3) << 3;
                cp_async16(As + m * L::LDA + kk, A + (size_t)(m0 + m) * lda + k0 + kk);
            } else {                       // 32 k-rows x 256 m
                int k = c >> 5, mm = (c & 31) << 3;
                cp_async16(As + k * L::LDA + mm, A + (size_t)(k0 + k) * lda + m0 + mm);
            }
        }
#pragma unroll
        for (int c = t; c < 512; c += 256) {
            if (BROW) {                    // 32 k-rows x 128 n
                int k = c >> 4, nn = (c & 15) << 3;
                cp_async16(Bs + k * L::LDB + nn, B + (size_t)(k0 + k) * ldb + n0 + nn);
            } else {                       // 128 n-rows x 32 k
                int n = c >> 2, kk = (c & 3) << 3;
                cp_async16(Bs + n * L::LDB + kk, B + (size_t)(n0 + n) * ldb + k0 + kk);
            }
        }
    };

    const int KT = K >> 5;
    // 3-stage prologue: stages 0, 1 in flight
    load_stage(0, 0);
    cp_commit();
    if (KT > 1) load_stage(1, 32);
    cp_commit();

    int sidx = 0;                    // kt % 3
    for (int kt = 0; kt < KT; kt++) {
        int pf = kt + 2;
        if (pf < KT) {
            int pb = pf - 3 * (pf / 3);
            load_stage(pb, pf << 5);
        }
        cp_commit();                 // uniform group accounting
        cp_wait<2>();                // stage kt resident
        __syncthreads();

        const __nv_bfloat16* As = smemh + sidx * L::STG;
        const __nv_bfloat16* Bs = As + L::ASTG;
#pragma unroll
        for (int ks = 0; ks < 32; ks += 16) {
#pragma unroll
            for (int i = 0; i < 4; i++) {
                const __nv_bfloat16* ap = AROW
                    ? As + (wm * 64 + i * 16) * L::LDA + ks
                    : As + ks * L::LDA + (wm * 64 + i * 16);
                wmma::load_matrix_sync(af[i], ap, L::LDA);
            }
#pragma unroll
            for (int j = 0; j < 4; j++) {
                const __nv_bfloat16* bp = BROW
                    ? Bs + ks * L::LDB + (wn * 64 + j * 16)
                    : Bs + (wn * 64 + j * 16) * L::LDB + ks;
                wmma::load_matrix_sync(bf[j], bp, L::LDB);
            }
#pragma unroll
            for (int i = 0; i < 4; i++)
#pragma unroll
                for (int j = 0; j < 4; j++)
                    wmma::mma_sync(acc[i][j], af[i], bf[j], acc[i][j]);
        }
        __syncthreads();
        if (++sidx == 3) sidx = 0;
    }

    // ---- epilogue: two 128-row halves through 128x132 fp32 staging ----
    float* Csh = (float*)smem_c;
#pragma unroll
    for (int h = 0; h < 2; h++) {
        if ((wm >> 1) == h) {
#pragma unroll
            for (int i = 0; i < 4; i++)
#pragma unroll
                for (int j = 0; j < 4; j++)
                    wmma::store_matrix_sync(
                        Csh + ((wm & 1) * 64 + i * 16) * 132 + wn * 64 + j * 16,
                        acc[i][j], 132, wmma::mem_row_major);
        }
        __syncthreads();

        const int c4 = (t & 31) << 2;
        for (int r = t >> 5; r < 128; r += 8) {
            float4 v = *(const float4*)(Csh + r * 132 + c4);
            const int m = m0 + h * 128 + r;
            float bsv = bias ? bias[m] : 0.f;
            v.x = v.x * alpha + bsv;
            v.y = v.y * alpha + bsv;
            v.z = v.z * alpha + bsv;
            v.w = v.w * alpha + bsv;
            if (R) {
                float4 rv = *(const float4*)(R + (size_t)m * N + n0 + c4);
                v.x += rv.x; v.y += rv.y; v.z += rv.z; v.w += rv.w;
            }
            OUT* cp = C + (size_t)m * N + n0 + c4;
            if (std::is_same<OUT, float>::value) {
                *(float4*)(void*)cp = v;
            } else {
                ushort4 u;
                u.x = __bfloat16_as_ushort(__float2bfloat16(v.x));
                u.y = __bfloat16_as_ushort(__float2bfloat16(v.y));
                u.z = __bfloat16_as_ushort(__float2bfloat16(v.z));
                u.w = __bfloat16_as_ushort(__float2bfloat16(v.w));
                *(ushort4*)(void*)cp = u;
            }
        }
        __syncthreads();
    }
}

// ============================================================
// Softmax: uint4 (16B) loads/stores, row cached in 16 regs.
// ============================================================
__global__ void __launch_bounds__(256) softmax_kernel(
    const __nv_bfloat16* __restrict__ S, __nv_bfloat16* __restrict__ Aout)
{
    const uint4* row4 = (const uint4*)(S + (size_t)blockIdx.x * HW);
    uint4* out4 = (uint4*)(Aout + (size_t)blockIdx.x * HW);
    const int t = threadIdx.x;
    __shared__ float sh[8];

    // 2 x 16B loads per thread -> 16 fp32 values
    uint4 d0 = row4[t];
    uint4 d1 = row4[t + 256];
    float vals[16];
    {
        const unsigned w[8] = {d0.x, d0.y, d0.z, d0.w, d1.x, d1.y, d1.z, d1.w};
#pragma unroll
        for (int k = 0; k < 8; k++) {
            __nv_bfloat162 h = *(const __nv_bfloat162*)&w[k];
            float2 f = __bfloat1622float2(h);
            vals[2 * k] = f.x; vals[2 * k + 1] = f.y;
        }
    }

    float m = -1e30f;
#pragma unroll
    for (int k = 0; k < 16; k++) m = fmaxf(m, vals[k]);
    for (int o = 16; o; o >>= 1) m = fmaxf(m, __shfl_xor_sync(0xffffffffu, m, o));
    if ((t & 31) == 0) sh[t >> 5] = m;
    __syncthreads();
    m = sh[0];
#pragma unroll
    for (int i = 1; i < 8; i++) m = fmaxf(m, sh[i]);

    float s = 0.f;
#pragma unroll
    for (int k = 0; k < 16; k++) {
        float e = __expf(vals[k] - m);
        vals[k] = e;
        s += e;
    }
    for (int o = 16; o; o >>= 1) s += __shfl_xor_sync(0xffffffffu, s, o);
    __syncthreads();
    if ((t & 31) == 0) sh[t >> 5] = s;
    __syncthreads();
    s = 0.f;
#pragma unroll
    for (int i = 0; i < 8; i++) s += sh[i];
    float inv = 1.f / s;

    unsigned wo[8];
#pragma unroll
    for (int k = 0; k < 8; k++) {
        __nv_bfloat162 h = __floats2bfloat162_rn(vals[2 * k] * inv, vals[2 * k + 1] * inv);
        wo[k] = *(const unsigned*)&h;
    }
    out4[t]       = make_uint4(wo[0], wo[1], wo[2], wo[3]);
    out4[t + 256] = make_uint4(wo[4], wo[5], wo[6], wo[7]);
}

// ============================================================
// Launch
// ============================================================
extern "C" void kernel_launch(void* const* d_in, const int* in_sizes, int n_in,
                              void* d_out, int out_size)
{
    const float* x      = (const float*)d_in[0];
    const float* gamma  = (const float*)d_in[1];
    const float* beta   = (const float*)d_in[2];
    const float* qkv_w  = (const float*)d_in[3];
    const float* qkv_b  = (const float*)d_in[4];
    const float* proj_w = (const float*)d_in[5];
    const float* proj_b = (const float*)d_in[6];
    float* out = (float*)d_out;

    __nv_bfloat16 *hn, *qkv, *scores, *attn, *ao, *qw, *pw;
    float* stat;
    cudaGetSymbolAddress((void**)&hn, g_hn);
    cudaGetSymbolAddress((void**)&qkv, g_qkv);
    cudaGetSymbolAddress((void**)&scores, g_scores);
    cudaGetSymbolAddress((void**)&attn, g_attn);
    cudaGetSymbolAddress((void**)&ao, g_ao);
    cudaGetSymbolAddress((void**)&qw, g_qw_h);
    cudaGetSymbolAddress((void**)&pw, g_pw_h);
    cudaGetSymbolAddress((void**)&stat, g_gnstat);

    cudaFuncSetAttribute(gemm_big<true,  true,  __nv_bfloat16>, cudaFuncAttributeMaxDynamicSharedMemorySize, BigLay<true,  true >::BYTES);
    cudaFuncSetAttribute(gemm_big<false, true,  __nv_bfloat16>, cudaFuncAttributeMaxDynamicSharedMemorySize, BigLay<false, true >::BYTES);
    cudaFuncSetAttribute(gemm_big<true,  false, __nv_bfloat16>, cudaFuncAttributeMaxDynamicSharedMemorySize, BigLay<true,  false>::BYTES);
    cudaFuncSetAttribute(gemm_big<true,  true,  float>,         cudaFuncAttributeMaxDynamicSharedMemorySize, BigLay<true,  true >::BYTES);

    // 0) GroupNorm stats + weight conversions (fused, one launch)
    gn_stats_cvt<<<1024, 256>>>(x, stat, qkv_w, qw, proj_w, pw);

    // 1) GroupNorm apply -> bf16 hn
    gn_apply<<<BB * CC, 256>>>(x, stat, gamma, beta, hn);

    // 2) QKV = W_qkv @ hn + b
    {
        dim3 grid(HW / 128, NQKV / 256, BB);
        gemm_big<true, true, __nv_bfloat16><<<grid, 256, BigLay<true, true>::BYTES>>>(
            qw, hn, qkv_b, nullptr, qkv,
            CC, HW, CC, HW,
            0, (size_t)CC * HW, (size_t)NQKV * HW, 0, 1.f);
    }

    // 3) scores = scale * Q^T K
    {
        dim3 grid(HW / 128, HW / 256, BB);
        gemm_big<false, true, __nv_bfloat16><<<grid, 256, BigLay<false, true>::BYTES>>>(
            qkv, qkv + (size_t)CC * HW, nullptr, nullptr, scores,
            CC, HW, HW, HW,
            (size_t)NQKV * HW, (size_t)NQKV * HW, (size_t)HW * HW, 0,
            0.04419417382415922f);
    }

    // 4) softmax rows -> bf16
    softmax_kernel<<<BB * HW, 256>>>(scores, attn);

    // 5) attnout = V @ attn^T
    {
        dim3 grid(HW / 128, CC / 256, BB);
        gemm_big<true, false, __nv_bfloat16><<<grid, 256, BigLay<true, false>::BYTES>>>(
            qkv + (size_t)2 * CC * HW, attn, nullptr, nullptr, ao,
            HW, HW, HW, HW,
            (size_t)NQKV * HW, (size_t)HW * HW, (size_t)CC * HW, 0, 1.f);
    }

    // 6) out = x + proj_w @ attnout + proj_b
    {
        dim3 grid(HW / 128, CC / 256, BB);
        gemm_big<true, true, float><<<grid, 256, BigLay<true, true>::BYTES>>>(
            pw, ao, proj_b, x, out,
            CC, HW, CC, HW,
            0, (size_t)CC * HW, (size_t)CC * HW, (size_t)CC * HW, 1.f);
    }
}